// round 14
// baseline (speedup 1.0000x reference)
#include <cuda_runtime.h>
#include <cuda_fp16.h>
#include <math.h>

// OutputNetwork, factored pipeline (v2):
//  K1 build: radial MLP tabulated on kink-aligned grid (h=step/12), norms
//     folded -> g_tab0[385][64], g_tab1[385][32], g_tab2[385][16] fp32.
//     97 blocks, 1 pass, float4 staging, ILP-2 dots.
//  K2 contract: G[zb][row][c] = sum_m T_c[row][m]*feats[z][b][map(c,m)], c=0..8,
//     via fp16 mma.sync. Operands staged ONCE (channel-contiguous 240 cols),
//     15 k-steps back-to-back, single barrier pair. fp16 out [zb][448][16].
//  K3 main: per pair: segment-confined quintic weights, 6 G-row loads (32B),
//     interp + Y-combine; warp = one a, lane = 2 b; butterfly -> softplus.

#define NRR   385
#define GROWS 448

__device__ float  g_tab0[NRR * 64];
__device__ float  g_tab1[NRR * 32];
__device__ float  g_tab2[NRR * 16];
__device__ __half g_G[4096UL * GROWS * 16];

#define BSMEM_BYTES (31744 * 4)

// ---- contract SMEM (bytes): As/Bs stride 264 halves (528B, bank-rotating) ----
#define K2_AS   0
#define K2_BS   33792
#define K2_CS   67584          // Cs [64 b][64 row][16 half] = 131072
#define K2_FS   198656
#define K2_SMEM 198720

__device__ __forceinline__ unsigned smem_u32(const void* p) {
    unsigned a;
    asm("{ .reg .u64 t; cvta.to.shared.u64 t, %1; cvt.u32.u64 %0, t; }" : "=r"(a) : "l"(p));
    return a;
}
__device__ __forceinline__ void ldm4(unsigned& r0, unsigned& r1, unsigned& r2, unsigned& r3,
                                     unsigned addr) {
    asm volatile("ldmatrix.sync.aligned.m8n8.x4.shared.b16 {%0, %1, %2, %3}, [%4];"
                 : "=r"(r0), "=r"(r1), "=r"(r2), "=r"(r3) : "r"(addr));
}
__device__ __forceinline__ void mma4(float* c, unsigned a0, unsigned a1, unsigned a2,
                                     unsigned a3, unsigned b0, unsigned b1) {
    asm volatile("mma.sync.aligned.m16n8k16.row.col.f32.f16.f16.f32 "
                 "{%0, %1, %2, %3}, {%4, %5, %6, %7}, {%8, %9}, {%0, %1, %2, %3};"
                 : "+f"(c[0]), "+f"(c[1]), "+f"(c[2]), "+f"(c[3])
                 : "r"(a0), "r"(a1), "r"(a2), "r"(a3), "r"(b0), "r"(b1));
}
__device__ __forceinline__ float ssp_precise(float x) {
    float bx = 5.0f * x;
    return (fmaxf(bx, 0.0f) + log1pf(expf(-fabsf(bx))) - 0.69314718055994531f) * 0.2f;
}

// ============================ K1: build table ============================
__global__ void __launch_bounds__(512, 1)
build_table_kernel(const float* __restrict__ W1,
                   const float* __restrict__ W2,
                   const float* __restrict__ W3)
{
    extern __shared__ float bs[];
    float* W2s = bs;              // [128][128]
    float* W3s = bs + 16384;      // [128][112]
    float* h1s = bs + 30720;      // [4][128]
    float* h2s = bs + 31232;      // [4][128]

    const int t  = threadIdx.x;
    const int rg = t >> 7;
    const int tl = t & 127;

    {
        const float4* g2 = (const float4*)W2;  float4* s2 = (float4*)W2s;
        const float4* g3 = (const float4*)W3;  float4* s3 = (float4*)W3s;
        #pragma unroll 8
        for (int i = t; i < 4096; i += 512) s2[i] = g2[i];
        #pragma unroll 7
        for (int i = t; i < 3584; i += 512) s3[i] = g3[i];
    }
    __syncthreads();

    const float RS32  = 0.17677669529663687f;
    const float RS128 = 0.08838834764831843f;

    const int row = blockIdx.x * 4 + rg;     // 0..387
    const bool live = (row < NRR);
    const float r = (float)row / 37.2f;

    float pre0 = 0.0f, pre1 = 0.0f;
    #pragma unroll
    for (int kb = 0; kb < 32; kb += 2) {
        float d0 = r * 3.1f - (float)kb;
        float d1 = d0 - 1.0f;
        float w0 = (fabsf(d0) < 1.0f) ? cosf(1.5707963267948966f * d0) : 0.0f;
        float w1 = (fabsf(d1) < 1.0f) ? cosf(1.5707963267948966f * d1) : 0.0f;
        pre0 = fmaf(w0, W1[kb * 128 + tl], pre0);
        pre1 = fmaf(w1, W1[(kb + 1) * 128 + tl], pre1);
    }
    h1s[rg * 128 + tl] = ssp_precise((pre0 + pre1) * RS32);
    __syncthreads();

    float a2a = 0.0f, a2b = 0.0f;
    #pragma unroll 8
    for (int k = 0; k < 128; k += 2) {
        a2a = fmaf(h1s[rg * 128 + k],     W2s[k * 128 + tl],       a2a);
        a2b = fmaf(h1s[rg * 128 + k + 1], W2s[(k + 1) * 128 + tl], a2b);
    }
    h2s[rg * 128 + tl] = ssp_precise((a2a + a2b) * RS128);
    __syncthreads();

    if (live && tl < 112) {
        float a3a = 0.0f, a3b = 0.0f;
        #pragma unroll 8
        for (int k = 0; k < 128; k += 2) {
            a3a = fmaf(h2s[rg * 128 + k],     W3s[k * 112 + tl],       a3a);
            a3b = fmaf(h2s[rg * 128 + k + 1], W3s[(k + 1) * 112 + tl], a3b);
        }
        const float norm = (tl < 64) ? 0.125f
                         : (tl < 96) ? 0.10206207261596575f
                                     : 0.11180339887498948f;
        const float val = (a3a + a3b) * RS128 * norm;
        if (tl < 64)      g_tab0[row * 64 + tl] = val;
        else if (tl < 96) g_tab1[row * 32 + (tl - 64)] = val;
        else              g_tab2[row * 16 + (tl - 96)] = val;
    }
}

// ============================ K2: contract (mma, single-stage) ============================
__global__ void __launch_bounds__(512, 1)
contract_kernel(const float* __restrict__ rep,
                const float* __restrict__ mask)
{
    extern __shared__ char cs[];
    __half* As  = (__half*)(cs + K2_AS);   // [64 b][264]
    __half* Bs  = (__half*)(cs + K2_BS);   // [64 row][264]
    __half* Cs  = (__half*)(cs + K2_CS);   // [64 b][64 row][16]
    float*  fsS = (float*)(cs + K2_FS);

    const int z  = blockIdx.y;
    const int rt = blockIdx.x;     // row tile (64 rows)
    const int t  = threadIdx.x;

    if (t < 32) {
        float m = mask[z * 64 + t] + mask[z * 64 + 32 + t];
        #pragma unroll
        for (int o = 16; o > 0; o >>= 1) m += __shfl_xor_sync(0xffffffff, m, o);
        if (t == 0) fsS[0] = rsqrtf(m);
    }
    __syncthreads();
    const float fs = fsS[0];

    // ---- single staging: channel-contiguous 240 columns ----
    {
        const int col = t & 255;
        const int g0  = t >> 8;        // 0/1
        if (col < 240) {
            int fj;
            if (col < 64)       fj = col;
            else if (col < 160) fj = 64 + 3 * ((col - 64) & 31) + ((col - 64) >> 5);
            else                fj = 160 + 5 * ((col - 160) & 15) + ((col - 160) >> 4);
            #pragma unroll 4
            for (int b = g0; b < 64; b += 2)
                As[b * 264 + col] =
                    __float2half_rn(fs * rep[(size_t)(z * 64 + b) * 240 + fj]);
            #pragma unroll 4
            for (int n = g0; n < 64; n += 2) {
                const int grow = rt * 64 + n;
                float v = 0.0f;
                if (grow < NRR) {
                    if (col < 64)       v = g_tab0[grow * 64 + col];
                    else if (col < 160) v = g_tab1[grow * 32 + ((col - 64) & 31)];
                    else                v = g_tab2[grow * 16 + ((col - 160) & 15)];
                }
                Bs[n * 264 + col] = __float2half_rn(v);
            }
        }
    }
    __syncthreads();

    // ---- warp tiles: 16 warps = 4 (b-tile) x 4 (row-tile), m16n16 each ----
    const int w    = t >> 5;
    const int lane = t & 31;
    const int mtile = w >> 2;
    const int ntile = w & 3;
    const int mi = lane >> 3, l7 = lane & 7;
    const unsigned AsU = smem_u32(As);
    const unsigned BsU = smem_u32(Bs);
    const int ar  = mtile * 16 + (mi & 1) * 8 + l7;
    const int ac  = (mi >> 1) * 8;
    const int bk  = (mi & 1) * 8;
    const int bts = mi >> 1;
    const int rb  = lane >> 2, cq = lane & 3;

    const int kc_start[9] = {0, 64, 96, 128, 160, 176, 192, 208, 224};
    const int kc_n[9]     = {4, 2, 2, 2, 1, 1, 1, 1, 1};

    #pragma unroll 1
    for (int c = 0; c < 9; c++) {
        float acc[2][4] = {{0.f, 0.f, 0.f, 0.f}, {0.f, 0.f, 0.f, 0.f}};
        #pragma unroll
        for (int s_ = 0; s_ < 4; s_++) {
            if (s_ >= kc_n[c]) break;
            const int kcol = kc_start[c] + 16 * s_;
            unsigned a0, a1, a2, a3;
            ldm4(a0, a1, a2, a3, AsU + (unsigned)((ar * 264 + kcol + ac) * 2));
            unsigned r0, r1, r2, r3;
            ldm4(r0, r1, r2, r3,
                 BsU + (unsigned)(((ntile * 16 + bts * 8 + l7) * 264 + kcol + bk) * 2));
            mma4(acc[0], a0, a1, a2, a3, r0, r1);
            mma4(acc[1], a0, a1, a2, a3, r2, r3);
        }
        const int b0r = mtile * 16 + rb;
        #pragma unroll
        for (int nt = 0; nt < 2; nt++) {
            const int n0 = ntile * 16 + nt * 8 + 2 * cq;
            Cs[(b0r * 64 + n0) * 16 + c]           = __float2half_rn(acc[nt][0]);
            Cs[(b0r * 64 + n0 + 1) * 16 + c]       = __float2half_rn(acc[nt][1]);
            Cs[((b0r + 8) * 64 + n0) * 16 + c]     = __float2half_rn(acc[nt][2]);
            Cs[((b0r + 8) * 64 + n0 + 1) * 16 + c] = __float2half_rn(acc[nt][3]);
        }
    }
    __syncthreads();

    // ---- coalesced writeout ----
    const uint4* c4 = (const uint4*)Cs;
    uint4* g4 = (uint4*)g_G;
    #pragma unroll 4
    for (int i = t; i < 8192; i += 512) {
        const int b = i >> 7, rem = i & 127;
        g4[((size_t)(z * 64 + b) * GROWS + rt * 64) * 2 + rem] = c4[i];
    }
}

// ============================ K3: main ============================
__global__ void __launch_bounds__(512)
output_network_kernel(const float* __restrict__ geo,
                      const float* __restrict__ mask,
                      float* __restrict__ out)
{
    __shared__ float geoS[192];

    const int t = threadIdx.x;
    const int z = blockIdx.x >> 2;
    const int q = blockIdx.x & 3;

    if (t < 192) geoS[t] = geo[z * 192 + t];
    __syncthreads();

    const int wid  = t >> 5;
    const int lane = t & 31;
    const int a    = q * 16 + wid;
    const float gax = geoS[a * 3 + 0];
    const float gay = geoS[a * 3 + 1];
    const float gaz = geoS[a * 3 + 2];

    const float S3  = 1.7320508075688772f;
    const float S5  = 2.2360679774997896f;
    const float S15 = 3.872983346207417f;

    float tot = 0.0f;
    #pragma unroll
    for (int i = 0; i < 2; i++) {
        const int b = lane + 32 * i;
        const float rx = gax - geoS[b * 3 + 0];
        const float ry = gay - geoS[b * 3 + 1];
        const float rz = gaz - geoS[b * 3 + 2];
        const float r2 = rx * rx + ry * ry + rz * rz;
        const float r  = sqrtf(fmaxf(r2, 1e-12f));
        const float nz = (r2 > 1e-10f) ? 1.0f : 0.0f;
        const float inv = 1.0f / r;
        const float xh = rx * inv, yh = ry * inv, zh = rz * inv;
        float yv[8];
        yv[0] = S3 * xh * nz;
        yv[1] = S3 * yh * nz;
        yv[2] = S3 * zh * nz;
        yv[3] = S15 * xh * yh * nz;
        yv[4] = S15 * yh * zh * nz;
        yv[5] = 0.5f * S5 * (3.0f * zh * zh - 1.0f) * nz;
        yv[6] = S15 * xh * zh * nz;
        yv[7] = 0.5f * S15 * (xh * xh - yh * yh) * nz;

        float u = r * 37.2f;
        const float sup = (u < 384.0f) ? 1.0f : 0.0f;
        u = fminf(u, 383.99f);
        int sg = (int)(u * 0.0833333333f);
        sg = (sg > 31) ? 31 : sg;
        const float xi = u - 12.0f * (float)sg;
        int s0 = (int)xi - 2;
        s0 = (s0 < 0) ? 0 : ((s0 > 7) ? 7 : s0);
        const float tt = xi - (float)s0;
        const int gs = 12 * sg + s0;

        const float p0 = tt,        p1 = tt - 1.0f, p2 = tt - 2.0f;
        const float p3 = tt - 3.0f, p4 = tt - 4.0f, p5 = tt - 5.0f;
        const float pr2 = p0 * p1, pr3 = pr2 * p2, pr4 = pr3 * p3, pr5 = pr4 * p4;
        const float sf3 = p4 * p5, sf2 = p3 * sf3, sf1 = p2 * sf2, sf0 = p1 * sf1;
        float wgt[6];
        wgt[0] = sup * (-8.3333333333e-3f) * sf0;
        wgt[1] = sup * ( 4.1666666667e-2f) * p0 * sf1;
        wgt[2] = sup * (-8.3333333333e-2f) * pr2 * sf2;
        wgt[3] = sup * ( 8.3333333333e-2f) * pr3 * sf3;
        wgt[4] = sup * (-4.1666666667e-2f) * pr4 * p5;
        wgt[5] = sup * ( 8.3333333333e-3f) * pr5;

        const __half* hp = g_G + ((size_t)(z * 64 + b) * GROWS + gs) * 16;
        float R[9];
        #pragma unroll
        for (int c = 0; c < 9; c++) R[c] = 0.0f;
        #pragma unroll
        for (int k = 0; k < 6; k++) {
            const uint4 v = *(const uint4*)(hp + k * 16);
            const unsigned v8 = *(const unsigned*)(hp + k * 16 + 8);
            const float wk = wgt[k];
            float2 c01 = __half22float2(*(const __half2*)&v.x);
            float2 c23 = __half22float2(*(const __half2*)&v.y);
            float2 c45 = __half22float2(*(const __half2*)&v.z);
            float2 c67 = __half22float2(*(const __half2*)&v.w);
            float2 c8x = __half22float2(*(const __half2*)&v8);
            R[0] = fmaf(wk, c01.x, R[0]);
            R[1] = fmaf(wk, c01.y, R[1]);
            R[2] = fmaf(wk, c23.x, R[2]);
            R[3] = fmaf(wk, c23.y, R[3]);
            R[4] = fmaf(wk, c45.x, R[4]);
            R[5] = fmaf(wk, c45.y, R[5]);
            R[6] = fmaf(wk, c67.x, R[6]);
            R[7] = fmaf(wk, c67.y, R[7]);
            R[8] = fmaf(wk, c8x.x, R[8]);
        }
        float ct = R[0];
        ct = fmaf(yv[0], R[1], ct);
        ct = fmaf(yv[1], R[2], ct);
        ct = fmaf(yv[2], R[3], ct);
        ct = fmaf(yv[3], R[4], ct);
        ct = fmaf(yv[4], R[5], ct);
        ct = fmaf(yv[5], R[6], ct);
        ct = fmaf(yv[6], R[7], ct);
        ct = fmaf(yv[7], R[8], ct);
        tot += ct;
    }

    tot += __shfl_xor_sync(0xffffffff, tot, 16);
    tot += __shfl_xor_sync(0xffffffff, tot, 8);
    tot += __shfl_xor_sync(0xffffffff, tot, 4);
    tot += __shfl_xor_sync(0xffffffff, tot, 2);
    tot += __shfl_xor_sync(0xffffffff, tot, 1);
    if (lane == 0) {
        const float bx = 5.0f * tot;
        const float sp = (fmaxf(bx, 0.0f) + log1pf(expf(-fabsf(bx)))) * 0.2f;
        out[z * 64 + a] = sp * mask[z * 64 + a];
    }
}

extern "C" void kernel_launch(void* const* d_in, const int* in_sizes, int n_in,
                              void* d_out, int out_size)
{
    const float* rep  = (const float*)d_in[0];
    const float* geo  = (const float*)d_in[1];
    const float* mask = (const float*)d_in[2];
    const float* W1   = (const float*)d_in[3];
    const float* W2   = (const float*)d_in[4];
    const float* W3   = (const float*)d_in[5];
    float* out = (float*)d_out;

    cudaFuncSetAttribute(build_table_kernel,
                         cudaFuncAttributeMaxDynamicSharedMemorySize, BSMEM_BYTES);
    cudaFuncSetAttribute(contract_kernel,
                         cudaFuncAttributeMaxDynamicSharedMemorySize, K2_SMEM);

    build_table_kernel<<<97, 512, BSMEM_BYTES>>>(W1, W2, W3);
    contract_kernel<<<dim3(7, 64), 512, K2_SMEM>>>(rep, mask);
    output_network_kernel<<<256, 512>>>(geo, mask, out);
}

// round 15
// speedup vs baseline: 2.1480x; 2.1480x over previous
#include <cuda_runtime.h>
#include <cuda_fp16.h>
#include <math.h>

// OutputNetwork, in-SMEM factored pipeline:
//  K1 build: radial MLP tabulated on kink-aligned grid (h=step/12), 2-sparse
//     basis (1 sincos), norms folded -> fp16 padded tables
//     g_tab0h[448][72], g_tab1h[448][40], g_tab2h[448][24] (pad rows zero).
//  K2 main: CTA = (z, b-quarter). mma-contract G[16b][448row][9ch] fp16 into
//     SMEM (143KB), then hot loop: per pair segment-confined quintic interp of
//     G (6 taps x 9ch) + Y-combine. Partials (4 per a) -> g_part.
//  K3 finish: sum 4 partials, softplus, mask.

#define NRR 385
#define GR  448

__device__ __half g_tab0h[GR * 72];
__device__ __half g_tab1h[GR * 40];
__device__ __half g_tab2h[GR * 24];
__device__ float  g_part[16384];

#define BSMEM_BYTES (31744 * 4)

// ---- main kernel SMEM (bytes) ----
#define GS_OFF   0         // Gs [16 b][448 row][10 ch] half = 143360
#define TB_OFF   143360    // Tb up to [448][72] half = 64512
#define AS_OFF   207872    // As [16 b][240] half = 7680
#define GEO_OFF  215552    // 192 floats
#define FS_OFF   216320
#define MSMEM_BYTES 216352

__device__ __forceinline__ unsigned smem_u32(const void* p) {
    unsigned a;
    asm("{ .reg .u64 t; cvta.to.shared.u64 t, %1; cvt.u32.u64 %0, t; }" : "=r"(a) : "l"(p));
    return a;
}
__device__ __forceinline__ void ldm4(unsigned& r0, unsigned& r1, unsigned& r2, unsigned& r3,
                                     unsigned addr) {
    asm volatile("ldmatrix.sync.aligned.m8n8.x4.shared.b16 {%0, %1, %2, %3}, [%4];"
                 : "=r"(r0), "=r"(r1), "=r"(r2), "=r"(r3) : "r"(addr));
}
__device__ __forceinline__ void mma4(float* c, unsigned a0, unsigned a1, unsigned a2,
                                     unsigned a3, unsigned b0, unsigned b1) {
    asm volatile("mma.sync.aligned.m16n8k16.row.col.f32.f16.f16.f32 "
                 "{%0, %1, %2, %3}, {%4, %5, %6, %7}, {%8, %9}, {%0, %1, %2, %3};"
                 : "+f"(c[0]), "+f"(c[1]), "+f"(c[2]), "+f"(c[3])
                 : "r"(a0), "r"(a1), "r"(a2), "r"(a3), "r"(b0), "r"(b1));
}
__device__ __forceinline__ float ssp_precise(float x) {
    float bx = 5.0f * x;
    return (fmaxf(bx, 0.0f) + log1pf(expf(-fabsf(bx))) - 0.69314718055994531f) * 0.2f;
}

// ============================ K1: build tables ============================
__global__ void __launch_bounds__(512, 1)
build_table_kernel(const float* __restrict__ W1,
                   const float* __restrict__ W2,
                   const float* __restrict__ W3)
{
    extern __shared__ float bs[];
    float* W2s = bs;              // [128][128]
    float* W3s = bs + 16384;      // [128][112]
    float* h1s = bs + 30720;      // [4][128]
    float* h2s = bs + 31232;      // [4][128]

    const int t  = threadIdx.x;
    const int rg = t >> 7;
    const int tl = t & 127;

    {
        const float4* g2 = (const float4*)W2;  float4* s2 = (float4*)W2s;
        const float4* g3 = (const float4*)W3;  float4* s3 = (float4*)W3s;
        #pragma unroll 8
        for (int i = t; i < 4096; i += 512) s2[i] = g2[i];
        #pragma unroll 7
        for (int i = t; i < 3584; i += 512) s3[i] = g3[i];
    }
    __syncthreads();

    const float RS32  = 0.17677669529663687f;
    const float RS128 = 0.08838834764831843f;

    const int row = blockIdx.x * 4 + rg;     // 0..447
    const bool live = (row < NRR);

    // 2-sparse cosine basis at grid node: u = r*3.1 = row/12 exactly
    const int i0 = row / 12;
    const float d0 = (float)(row - 12 * i0) * (1.0f / 12.0f);
    float sv, cv;
    sincosf(1.5707963267948966f * d0, &sv, &cv);
    const float c0 = (i0 <= 31) ? cv : 0.0f;
    const float c1 = (i0 <= 30) ? sv : 0.0f;
    const int ia = (i0 > 31) ? 31 : i0;
    const int ib = (i0 + 1 > 31) ? 31 : (i0 + 1);
    const float pre = (c0 * W1[ia * 128 + tl] + c1 * W1[ib * 128 + tl]) * RS32;
    h1s[rg * 128 + tl] = ssp_precise(pre);
    __syncthreads();

    float a2a = 0.0f, a2b = 0.0f;
    #pragma unroll 8
    for (int k = 0; k < 128; k += 2) {
        a2a = fmaf(h1s[rg * 128 + k],     W2s[k * 128 + tl],       a2a);
        a2b = fmaf(h1s[rg * 128 + k + 1], W2s[(k + 1) * 128 + tl], a2b);
    }
    h2s[rg * 128 + tl] = ssp_precise((a2a + a2b) * RS128);
    __syncthreads();

    if (tl < 112) {
        float a3a = 0.0f, a3b = 0.0f;
        #pragma unroll 8
        for (int k = 0; k < 128; k += 2) {
            a3a = fmaf(h2s[rg * 128 + k],     W3s[k * 112 + tl],       a3a);
            a3b = fmaf(h2s[rg * 128 + k + 1], W3s[(k + 1) * 112 + tl], a3b);
        }
        const float norm = (tl < 64) ? 0.125f
                         : (tl < 96) ? 0.10206207261596575f
                                     : 0.11180339887498948f;
        const float valf = (a3a + a3b) * RS128 * norm;
        const __half v = __float2half_rn(live ? valf : 0.0f);
        if (tl < 64)      g_tab0h[row * 72 + tl] = v;
        else if (tl < 96) g_tab1h[row * 40 + (tl - 64)] = v;
        else              g_tab2h[row * 24 + (tl - 96)] = v;
    }
}

// ============================ K2: contract + main ============================
__global__ void __launch_bounds__(512, 1)
main_kernel(const float* __restrict__ rep,
            const float* __restrict__ geo,
            const float* __restrict__ mask)
{
    extern __shared__ char smc[];
    __half* Gs   = (__half*)(smc + GS_OFF);   // [16][448][10]
    __half* Tb   = (__half*)(smc + TB_OFF);
    __half* As   = (__half*)(smc + AS_OFF);   // [16][240]
    float*  geoS = (float*)(smc + GEO_OFF);
    float*  fsS  = (float*)(smc + FS_OFF);

    const int t  = threadIdx.x;
    const int z  = blockIdx.x >> 2;
    const int bq = blockIdx.x & 3;

    // ---- fscale + geo ----
    if (t < 32) {
        float m = mask[z * 64 + t] + mask[z * 64 + 32 + t];
        #pragma unroll
        for (int o = 16; o > 0; o >>= 1) m += __shfl_xor_sync(0xffffffff, m, o);
        if (t == 0) fsS[0] = rsqrtf(m);
    }
    if (t < 192) geoS[t] = geo[z * 192 + t];
    __syncthreads();
    const float fs = fsS[0];

    // ---- stage As: feats (channel-contiguous cols, fp16, fscale folded) ----
    if (t < 480) {
        const int col = t % 240;
        const int bs0 = t / 240;
        int fj;
        if (col < 64)       fj = col;
        else if (col < 160) fj = 64 + 3 * ((col - 64) & 31) + ((col - 64) >> 5);
        else                fj = 160 + 5 * ((col - 160) & 15) + ((col - 160) >> 4);
        #pragma unroll
        for (int b = bs0; b < 16; b += 2)
            As[b * 240 + col] =
                __float2half_rn(fs * rep[(size_t)(z * 64 + bq * 16 + b) * 240 + fj]);
    }

    const int w    = t >> 5;
    const int lane = t & 31;
    const unsigned AsU = smem_u32(As);
    const unsigned TbU = smem_u32(Tb);
    const int mi = lane >> 3, l7 = lane & 7;
    const int ar  = (mi & 1) * 8 + l7;
    const int ac  = (mi >> 1) * 8;
    const int bk  = (mi & 1) * 8;
    const int bts = mi >> 1;
    const int rb  = lane >> 2, cq = lane & 3;

    // ---- 3 sub-phases: stage T, mma channels, scatter to Gs ----
    #pragma unroll 1
    for (int ph = 0; ph < 3; ph++) {
        const int bstride = (ph == 0) ? 72 : ((ph == 1) ? 40 : 24);
        const int n4      = (ph == 0) ? 4032 : ((ph == 1) ? 2240 : 1344);
        const __half* gsrc = (ph == 0) ? g_tab0h : ((ph == 1) ? g_tab1h : g_tab2h);
        __syncthreads();
        {
            const uint4* s4 = (const uint4*)gsrc;
            uint4* d4 = (uint4*)Tb;
            for (int i = t; i < n4; i += 512) d4[i] = s4[i];
        }
        __syncthreads();

        if (w < 14) {
            const int nch    = (ph == 0) ? 1 : ((ph == 1) ? 3 : 5);
            const int ksteps = (ph == 0) ? 4 : ((ph == 1) ? 2 : 1);
            const int ch0    = (ph == 0) ? 0 : ((ph == 1) ? 1 : 4);
            const int ab0    = (ph == 0) ? 0 : ((ph == 1) ? 64 : 160);
            #pragma unroll 1
            for (int c = 0; c < nch; c++) {
                const int abase = ab0 + c * (ksteps * 16);
                const int ch = ch0 + c;
                float acc[4][4];
                #pragma unroll
                for (int i = 0; i < 4; i++) {
                    acc[i][0] = 0.f; acc[i][1] = 0.f; acc[i][2] = 0.f; acc[i][3] = 0.f;
                }
                #pragma unroll 4
                for (int ks = 0; ks < 4; ks++) {
                    if (ks >= ksteps) break;
                    unsigned a0, a1, a2, a3;
                    ldm4(a0, a1, a2, a3,
                         AsU + (unsigned)((ar * 240 + abase + ks * 16 + ac) * 2));
                    #pragma unroll
                    for (int p = 0; p < 2; p++) {
                        unsigned r0, r1, r2, r3;
                        ldm4(r0, r1, r2, r3,
                             TbU + (unsigned)(((w * 32 + (2 * p + bts) * 8 + l7) * bstride
                                               + ks * 16 + bk) * 2));
                        mma4(acc[2 * p],     a0, a1, a2, a3, r0, r1);
                        mma4(acc[2 * p + 1], a0, a1, a2, a3, r2, r3);
                    }
                }
                #pragma unroll
                for (int tile = 0; tile < 4; tile++) {
                    const int n0 = w * 32 + tile * 8 + 2 * cq;
                    Gs[(rb * 448 + n0) * 10 + ch]           = __float2half_rn(acc[tile][0]);
                    Gs[(rb * 448 + n0 + 1) * 10 + ch]       = __float2half_rn(acc[tile][1]);
                    Gs[((rb + 8) * 448 + n0) * 10 + ch]     = __float2half_rn(acc[tile][2]);
                    Gs[((rb + 8) * 448 + n0 + 1) * 10 + ch] = __float2half_rn(acc[tile][3]);
                }
            }
        }
    }
    __syncthreads();

    // ---- hot loop: warp w handles a = 4w..4w+3; lanes = 4a x 8b; 2 b-iters ----
    const int aloc = lane >> 3;
    const int a    = 4 * w + aloc;
    const int bl0  = lane & 7;
    const float gax = geoS[a * 3 + 0];
    const float gay = geoS[a * 3 + 1];
    const float gaz = geoS[a * 3 + 2];

    const float S3  = 1.7320508075688772f;
    const float S5  = 2.2360679774997896f;
    const float S15 = 3.872983346207417f;

    float tot = 0.0f;
    #pragma unroll
    for (int ii = 0; ii < 2; ii++) {
        const int bl = bl0 + 8 * ii;              // local b 0..15
        const int bg = bq * 16 + bl;              // global b
        const float rx = gax - geoS[bg * 3 + 0];
        const float ry = gay - geoS[bg * 3 + 1];
        const float rz = gaz - geoS[bg * 3 + 2];
        const float r2 = rx * rx + ry * ry + rz * rz;
        const float r  = sqrtf(fmaxf(r2, 1e-12f));
        const float nz = (r2 > 1e-10f) ? 1.0f : 0.0f;
        const float inv = 1.0f / r;
        const float xh = rx * inv, yh = ry * inv, zh = rz * inv;
        float yv[8];
        yv[0] = S3 * xh * nz;
        yv[1] = S3 * yh * nz;
        yv[2] = S3 * zh * nz;
        yv[3] = S15 * xh * yh * nz;
        yv[4] = S15 * yh * zh * nz;
        yv[5] = 0.5f * S5 * (3.0f * zh * zh - 1.0f) * nz;
        yv[6] = S15 * xh * zh * nz;
        yv[7] = 0.5f * S15 * (xh * xh - yh * yh) * nz;

        float u = r * 37.2f;
        const float sup = (u < 384.0f) ? 1.0f : 0.0f;
        u = fminf(u, 383.99f);
        int sg = (int)(u * 0.0833333333f);
        sg = (sg > 31) ? 31 : sg;
        const float xi = u - 12.0f * (float)sg;
        int s0 = (int)xi - 2;
        s0 = (s0 < 0) ? 0 : ((s0 > 7) ? 7 : s0);
        const float tt = xi - (float)s0;
        const int gs = 12 * sg + s0;

        const float p0 = tt,        p1 = tt - 1.0f, p2 = tt - 2.0f;
        const float p3 = tt - 3.0f, p4 = tt - 4.0f, p5 = tt - 5.0f;
        const float pr2 = p0 * p1, pr3 = pr2 * p2, pr4 = pr3 * p3, pr5 = pr4 * p4;
        const float sf3 = p4 * p5, sf2 = p3 * sf3, sf1 = p2 * sf2, sf0 = p1 * sf1;
        float wgt[6];
        wgt[0] = sup * (-8.3333333333e-3f) * sf0;
        wgt[1] = sup * ( 4.1666666667e-2f) * p0 * sf1;
        wgt[2] = sup * (-8.3333333333e-2f) * pr2 * sf2;
        wgt[3] = sup * ( 8.3333333333e-2f) * pr3 * sf3;
        wgt[4] = sup * (-4.1666666667e-2f) * pr4 * p5;
        wgt[5] = sup * ( 8.3333333333e-3f) * pr5;

        const __half* gp = Gs + (bl * 448 + gs) * 10;
        float R[9];
        #pragma unroll
        for (int c = 0; c < 9; c++) R[c] = 0.0f;
        #pragma unroll
        for (int k = 0; k < 6; k++) {
            const unsigned* hp = (const unsigned*)(gp + k * 10);
            const float wk = wgt[k];
            float2 c01 = __half22float2(*(const __half2*)&hp[0]);
            float2 c23 = __half22float2(*(const __half2*)&hp[1]);
            float2 c45 = __half22float2(*(const __half2*)&hp[2]);
            float2 c67 = __half22float2(*(const __half2*)&hp[3]);
            float2 c8x = __half22float2(*(const __half2*)&hp[4]);
            R[0] = fmaf(wk, c01.x, R[0]);
            R[1] = fmaf(wk, c01.y, R[1]);
            R[2] = fmaf(wk, c23.x, R[2]);
            R[3] = fmaf(wk, c23.y, R[3]);
            R[4] = fmaf(wk, c45.x, R[4]);
            R[5] = fmaf(wk, c45.y, R[5]);
            R[6] = fmaf(wk, c67.x, R[6]);
            R[7] = fmaf(wk, c67.y, R[7]);
            R[8] = fmaf(wk, c8x.x, R[8]);
        }
        float ct = R[0];
        ct = fmaf(yv[0], R[1], ct);
        ct = fmaf(yv[1], R[2], ct);
        ct = fmaf(yv[2], R[3], ct);
        ct = fmaf(yv[3], R[4], ct);
        ct = fmaf(yv[4], R[5], ct);
        ct = fmaf(yv[5], R[6], ct);
        ct = fmaf(yv[6], R[7], ct);
        ct = fmaf(yv[7], R[8], ct);
        tot += ct;
    }

    // reduce over 8-lane b-groups
    tot += __shfl_xor_sync(0xffffffff, tot, 1);
    tot += __shfl_xor_sync(0xffffffff, tot, 2);
    tot += __shfl_xor_sync(0xffffffff, tot, 4);
    if ((lane & 7) == 0)
        g_part[(z * 64 + a) * 4 + bq] = tot;
}

// ============================ K3: finish ============================
__global__ void __launch_bounds__(256)
finish_kernel(const float* __restrict__ mask, float* __restrict__ out)
{
    const int i = blockIdx.x * 256 + threadIdx.x;
    if (i < 4096) {
        const float tot = g_part[i * 4 + 0] + g_part[i * 4 + 1]
                        + g_part[i * 4 + 2] + g_part[i * 4 + 3];
        const float bx = 5.0f * tot;
        const float sp = (fmaxf(bx, 0.0f) + log1pf(expf(-fabsf(bx)))) * 0.2f;
        out[i] = sp * mask[i];
    }
}

extern "C" void kernel_launch(void* const* d_in, const int* in_sizes, int n_in,
                              void* d_out, int out_size)
{
    const float* rep  = (const float*)d_in[0];
    const float* geo  = (const float*)d_in[1];
    const float* mask = (const float*)d_in[2];
    const float* W1   = (const float*)d_in[3];
    const float* W2   = (const float*)d_in[4];
    const float* W3   = (const float*)d_in[5];
    float* out = (float*)d_out;

    cudaFuncSetAttribute(build_table_kernel,
                         cudaFuncAttributeMaxDynamicSharedMemorySize, BSMEM_BYTES);
    cudaFuncSetAttribute(main_kernel,
                         cudaFuncAttributeMaxDynamicSharedMemorySize, MSMEM_BYTES);

    build_table_kernel<<<112, 512, BSMEM_BYTES>>>(W1, W2, W3);
    main_kernel<<<256, 512, MSMEM_BYTES>>>(rep, geo, mask);
    finish_kernel<<<16, 256>>>(mask, out);
}

// round 16
// speedup vs baseline: 3.2002x; 1.4898x over previous
#include <cuda_runtime.h>
#include <cuda_fp16.h>
#include <math.h>

// OutputNetwork, in-SMEM factored pipeline (v2: coarse grid, 2 CTAs/SM):
//  K1 build: radial MLP tabulated on kink-aligned grid h = step/6 (6 intervals
//     per cosine-window segment; 193 live rows, padded to 224), 2-sparse basis,
//     norms folded -> fp16 tables g_tab0h[224][72], g_tab1h[224][40],
//     g_tab2h[224][24].
//  K2 main: CTA = (z, b-quarter), 512 thr, ~110KB SMEM -> 2 CTAs/SM, 1 wave.
//     mma-contract G[16b][224row][9ch] fp16 into SMEM, then hot loop:
//     segment-confined quintic interp (6-tap = whole segment) + Y-combine.
//  K3 finish: sum 4 partials, softplus, mask.

#define NLIVE 193
#define GR    224

__device__ __half g_tab0h[GR * 72];
__device__ __half g_tab1h[GR * 40];
__device__ __half g_tab2h[GR * 24];
__device__ float  g_part[16384];

#define BSMEM_BYTES (31744 * 4)

// ---- main kernel SMEM (bytes) ----
#define GS_OFF   0         // Gs [16][224][10] half = 71680
#define TB_OFF   71680     // Tb up to [224][72] half = 32256
#define AS_OFF   103936    // As [16][240] half = 7680
#define GEO_OFF  111616    // 192 floats
#define FS_OFF   112384
#define MSMEM_BYTES 112416

__device__ __forceinline__ unsigned smem_u32(const void* p) {
    unsigned a;
    asm("{ .reg .u64 t; cvta.to.shared.u64 t, %1; cvt.u32.u64 %0, t; }" : "=r"(a) : "l"(p));
    return a;
}
__device__ __forceinline__ void ldm4(unsigned& r0, unsigned& r1, unsigned& r2, unsigned& r3,
                                     unsigned addr) {
    asm volatile("ldmatrix.sync.aligned.m8n8.x4.shared.b16 {%0, %1, %2, %3}, [%4];"
                 : "=r"(r0), "=r"(r1), "=r"(r2), "=r"(r3) : "r"(addr));
}
__device__ __forceinline__ void mma4(float* c, unsigned a0, unsigned a1, unsigned a2,
                                     unsigned a3, unsigned b0, unsigned b1) {
    asm volatile("mma.sync.aligned.m16n8k16.row.col.f32.f16.f16.f32 "
                 "{%0, %1, %2, %3}, {%4, %5, %6, %7}, {%8, %9}, {%0, %1, %2, %3};"
                 : "+f"(c[0]), "+f"(c[1]), "+f"(c[2]), "+f"(c[3])
                 : "r"(a0), "r"(a1), "r"(a2), "r"(a3), "r"(b0), "r"(b1));
}
__device__ __forceinline__ float ssp_precise(float x) {
    float bx = 5.0f * x;
    return (fmaxf(bx, 0.0f) + log1pf(expf(-fabsf(bx))) - 0.69314718055994531f) * 0.2f;
}

// ============================ K1: build tables ============================
__global__ void __launch_bounds__(512, 1)
build_table_kernel(const float* __restrict__ W1,
                   const float* __restrict__ W2,
                   const float* __restrict__ W3)
{
    extern __shared__ float bs[];
    float* W2s = bs;              // [128][128]
    float* W3s = bs + 16384;      // [128][112]
    float* h1s = bs + 30720;      // [4][128]
    float* h2s = bs + 31232;      // [4][128]

    const int t  = threadIdx.x;
    const int rg = t >> 7;
    const int tl = t & 127;

    {
        const float4* g2 = (const float4*)W2;  float4* s2 = (float4*)W2s;
        const float4* g3 = (const float4*)W3;  float4* s3 = (float4*)W3s;
        #pragma unroll 8
        for (int i = t; i < 4096; i += 512) s2[i] = g2[i];
        #pragma unroll 7
        for (int i = t; i < 3584; i += 512) s3[i] = g3[i];
    }
    __syncthreads();

    const float RS32  = 0.17677669529663687f;
    const float RS128 = 0.08838834764831843f;

    const int row = blockIdx.x * 4 + rg;     // 0..223
    const bool live = (row < NLIVE);

    // 2-sparse cosine basis at grid node: node units, centers every 6 nodes
    const int i0 = row / 6;
    const float d0 = (float)(row - 6 * i0) * (1.0f / 6.0f);
    float sv, cv;
    sincosf(1.5707963267948966f * d0, &sv, &cv);
    const float c0 = (i0 <= 31) ? cv : 0.0f;
    const float c1 = (i0 <= 30) ? sv : 0.0f;
    const int ia = (i0 > 31) ? 31 : i0;
    const int ib = (i0 + 1 > 31) ? 31 : (i0 + 1);
    const float pre = (c0 * W1[ia * 128 + tl] + c1 * W1[ib * 128 + tl]) * RS32;
    h1s[rg * 128 + tl] = ssp_precise(pre);
    __syncthreads();

    float a2a = 0.0f, a2b = 0.0f;
    #pragma unroll 8
    for (int k = 0; k < 128; k += 2) {
        a2a = fmaf(h1s[rg * 128 + k],     W2s[k * 128 + tl],       a2a);
        a2b = fmaf(h1s[rg * 128 + k + 1], W2s[(k + 1) * 128 + tl], a2b);
    }
    h2s[rg * 128 + tl] = ssp_precise((a2a + a2b) * RS128);
    __syncthreads();

    if (tl < 112) {
        float a3a = 0.0f, a3b = 0.0f;
        #pragma unroll 8
        for (int k = 0; k < 128; k += 2) {
            a3a = fmaf(h2s[rg * 128 + k],     W3s[k * 112 + tl],       a3a);
            a3b = fmaf(h2s[rg * 128 + k + 1], W3s[(k + 1) * 112 + tl], a3b);
        }
        const float norm = (tl < 64) ? 0.125f
                         : (tl < 96) ? 0.10206207261596575f
                                     : 0.11180339887498948f;
        const float valf = (a3a + a3b) * RS128 * norm;
        const __half v = __float2half_rn(live ? valf : 0.0f);
        if (tl < 64)      g_tab0h[row * 72 + tl] = v;
        else if (tl < 96) g_tab1h[row * 40 + (tl - 64)] = v;
        else              g_tab2h[row * 24 + (tl - 96)] = v;
    }
}

// ============================ K2: contract + main ============================
__global__ void __launch_bounds__(512, 2)
main_kernel(const float* __restrict__ rep,
            const float* __restrict__ geo,
            const float* __restrict__ mask)
{
    extern __shared__ char smc[];
    __half* Gs   = (__half*)(smc + GS_OFF);   // [16][224][10]
    __half* Tb   = (__half*)(smc + TB_OFF);
    __half* As   = (__half*)(smc + AS_OFF);   // [16][240]
    float*  geoS = (float*)(smc + GEO_OFF);
    float*  fsS  = (float*)(smc + FS_OFF);

    const int t  = threadIdx.x;
    const int z  = blockIdx.x >> 2;
    const int bq = blockIdx.x & 3;

    // ---- fscale + geo ----
    if (t < 32) {
        float m = mask[z * 64 + t] + mask[z * 64 + 32 + t];
        #pragma unroll
        for (int o = 16; o > 0; o >>= 1) m += __shfl_xor_sync(0xffffffff, m, o);
        if (t == 0) fsS[0] = rsqrtf(m);
    }
    if (t < 192) geoS[t] = geo[z * 192 + t];
    __syncthreads();
    const float fs = fsS[0];

    // ---- stage As: feats (channel-contiguous cols, fp16, fscale folded) ----
    if (t < 480) {
        const int col = t % 240;
        const int bs0 = t / 240;
        int fj;
        if (col < 64)       fj = col;
        else if (col < 160) fj = 64 + 3 * ((col - 64) & 31) + ((col - 64) >> 5);
        else                fj = 160 + 5 * ((col - 160) & 15) + ((col - 160) >> 4);
        #pragma unroll
        for (int b = bs0; b < 16; b += 2)
            As[b * 240 + col] =
                __float2half_rn(fs * rep[(size_t)(z * 64 + bq * 16 + b) * 240 + fj]);
    }

    const int w    = t >> 5;
    const int lane = t & 31;
    const unsigned AsU = smem_u32(As);
    const unsigned TbU = smem_u32(Tb);
    const int mi = lane >> 3, l7 = lane & 7;
    const int ar  = (mi & 1) * 8 + l7;
    const int ac  = (mi >> 1) * 8;
    const int bk  = (mi & 1) * 8;
    const int bts = mi >> 1;
    const int rb  = lane >> 2, cq = lane & 3;

    // ---- 3 sub-phases: stage T, mma channels, scatter to Gs ----
    #pragma unroll 1
    for (int ph = 0; ph < 3; ph++) {
        const int bstride = (ph == 0) ? 72 : ((ph == 1) ? 40 : 24);
        const int n4      = (ph == 0) ? 2016 : ((ph == 1) ? 1120 : 672);
        const __half* gsrc = (ph == 0) ? g_tab0h : ((ph == 1) ? g_tab1h : g_tab2h);
        __syncthreads();
        {
            const uint4* s4 = (const uint4*)gsrc;
            uint4* d4 = (uint4*)Tb;
            for (int i = t; i < n4; i += 512) d4[i] = s4[i];
        }
        __syncthreads();

        if (w < 7) {
            const int nch    = (ph == 0) ? 1 : ((ph == 1) ? 3 : 5);
            const int ksteps = (ph == 0) ? 4 : ((ph == 1) ? 2 : 1);
            const int ch0    = (ph == 0) ? 0 : ((ph == 1) ? 1 : 4);
            const int ab0    = (ph == 0) ? 0 : ((ph == 1) ? 64 : 160);
            #pragma unroll 1
            for (int c = 0; c < nch; c++) {
                const int abase = ab0 + c * (ksteps * 16);
                const int ch = ch0 + c;
                float acc[4][4];
                #pragma unroll
                for (int i = 0; i < 4; i++) {
                    acc[i][0] = 0.f; acc[i][1] = 0.f; acc[i][2] = 0.f; acc[i][3] = 0.f;
                }
                #pragma unroll 4
                for (int ks = 0; ks < 4; ks++) {
                    if (ks >= ksteps) break;
                    unsigned a0, a1, a2, a3;
                    ldm4(a0, a1, a2, a3,
                         AsU + (unsigned)((ar * 240 + abase + ks * 16 + ac) * 2));
                    #pragma unroll
                    for (int p = 0; p < 2; p++) {
                        unsigned r0, r1, r2, r3;
                        ldm4(r0, r1, r2, r3,
                             TbU + (unsigned)(((w * 32 + (2 * p + bts) * 8 + l7) * bstride
                                               + ks * 16 + bk) * 2));
                        mma4(acc[2 * p],     a0, a1, a2, a3, r0, r1);
                        mma4(acc[2 * p + 1], a0, a1, a2, a3, r2, r3);
                    }
                }
                #pragma unroll
                for (int tile = 0; tile < 4; tile++) {
                    const int n0 = w * 32 + tile * 8 + 2 * cq;
                    Gs[(rb * GR + n0) * 10 + ch]           = __float2half_rn(acc[tile][0]);
                    Gs[(rb * GR + n0 + 1) * 10 + ch]       = __float2half_rn(acc[tile][1]);
                    Gs[((rb + 8) * GR + n0) * 10 + ch]     = __float2half_rn(acc[tile][2]);
                    Gs[((rb + 8) * GR + n0 + 1) * 10 + ch] = __float2half_rn(acc[tile][3]);
                }
            }
        }
    }
    __syncthreads();

    // ---- hot loop: warp w handles a = 4w..4w+3; lanes = 4a x 8b; 2 b-iters ----
    const int aloc = lane >> 3;
    const int a    = 4 * w + aloc;
    const int bl0  = lane & 7;
    const float gax = geoS[a * 3 + 0];
    const float gay = geoS[a * 3 + 1];
    const float gaz = geoS[a * 3 + 2];

    const float S3  = 1.7320508075688772f;
    const float S5  = 2.2360679774997896f;
    const float S15 = 3.872983346207417f;

    float tot = 0.0f;
    #pragma unroll
    for (int ii = 0; ii < 2; ii++) {
        const int bl = bl0 + 8 * ii;              // local b 0..15
        const int bg = bq * 16 + bl;              // global b
        const float rx = gax - geoS[bg * 3 + 0];
        const float ry = gay - geoS[bg * 3 + 1];
        const float rz = gaz - geoS[bg * 3 + 2];
        const float r2 = rx * rx + ry * ry + rz * rz;
        const float r  = sqrtf(fmaxf(r2, 1e-12f));
        const float nz = (r2 > 1e-10f) ? 1.0f : 0.0f;
        const float inv = 1.0f / r;
        const float xh = rx * inv, yh = ry * inv, zh = rz * inv;
        float yv[8];
        yv[0] = S3 * xh * nz;
        yv[1] = S3 * yh * nz;
        yv[2] = S3 * zh * nz;
        yv[3] = S15 * xh * yh * nz;
        yv[4] = S15 * yh * zh * nz;
        yv[5] = 0.5f * S5 * (3.0f * zh * zh - 1.0f) * nz;
        yv[6] = S15 * xh * zh * nz;
        yv[7] = 0.5f * S15 * (xh * xh - yh * yh) * nz;

        // node units: u = r * 3.1 * 6
        float u = r * 18.6f;
        const float sup = (u < 192.0f) ? 1.0f : 0.0f;
        u = fminf(u, 191.99f);
        int sg = (int)(u * 0.16666667f);
        sg = (sg > 31) ? 31 : sg;
        const float xi = u - 6.0f * (float)sg;    // [0,6)
        int s0 = (int)xi - 2;
        s0 = (s0 < 0) ? 0 : ((s0 > 1) ? 1 : s0);
        const float tt = xi - (float)s0;          // [0,5)
        const int gs = 6 * sg + s0;               // taps gs..gs+5 <= 192

        const float p0 = tt,        p1 = tt - 1.0f, p2 = tt - 2.0f;
        const float p3 = tt - 3.0f, p4 = tt - 4.0f, p5 = tt - 5.0f;
        const float pr2 = p0 * p1, pr3 = pr2 * p2, pr4 = pr3 * p3, pr5 = pr4 * p4;
        const float sf3 = p4 * p5, sf2 = p3 * sf3, sf1 = p2 * sf2, sf0 = p1 * sf1;
        float wgt[6];
        wgt[0] = sup * (-8.3333333333e-3f) * sf0;
        wgt[1] = sup * ( 4.1666666667e-2f) * p0 * sf1;
        wgt[2] = sup * (-8.3333333333e-2f) * pr2 * sf2;
        wgt[3] = sup * ( 8.3333333333e-2f) * pr3 * sf3;
        wgt[4] = sup * (-4.1666666667e-2f) * pr4 * p5;
        wgt[5] = sup * ( 8.3333333333e-3f) * pr5;

        const __half* gp = Gs + (bl * GR + gs) * 10;
        float R[9];
        #pragma unroll
        for (int c = 0; c < 9; c++) R[c] = 0.0f;
        #pragma unroll
        for (int k = 0; k < 6; k++) {
            const unsigned* hp = (const unsigned*)(gp + k * 10);
            const float wk = wgt[k];
            float2 c01 = __half22float2(*(const __half2*)&hp[0]);
            float2 c23 = __half22float2(*(const __half2*)&hp[1]);
            float2 c45 = __half22float2(*(const __half2*)&hp[2]);
            float2 c67 = __half22float2(*(const __half2*)&hp[3]);
            float2 c8x = __half22float2(*(const __half2*)&hp[4]);
            R[0] = fmaf(wk, c01.x, R[0]);
            R[1] = fmaf(wk, c01.y, R[1]);
            R[2] = fmaf(wk, c23.x, R[2]);
            R[3] = fmaf(wk, c23.y, R[3]);
            R[4] = fmaf(wk, c45.x, R[4]);
            R[5] = fmaf(wk, c45.y, R[5]);
            R[6] = fmaf(wk, c67.x, R[6]);
            R[7] = fmaf(wk, c67.y, R[7]);
            R[8] = fmaf(wk, c8x.x, R[8]);
        }
        float ct = R[0];
        ct = fmaf(yv[0], R[1], ct);
        ct = fmaf(yv[1], R[2], ct);
        ct = fmaf(yv[2], R[3], ct);
        ct = fmaf(yv[3], R[4], ct);
        ct = fmaf(yv[4], R[5], ct);
        ct = fmaf(yv[5], R[6], ct);
        ct = fmaf(yv[6], R[7], ct);
        ct = fmaf(yv[7], R[8], ct);
        tot += ct;
    }

    // reduce over 8-lane b-groups
    tot += __shfl_xor_sync(0xffffffff, tot, 1);
    tot += __shfl_xor_sync(0xffffffff, tot, 2);
    tot += __shfl_xor_sync(0xffffffff, tot, 4);
    if ((lane & 7) == 0)
        g_part[(z * 64 + a) * 4 + bq] = tot;
}

// ============================ K3: finish ============================
__global__ void __launch_bounds__(256)
finish_kernel(const float* __restrict__ mask, float* __restrict__ out)
{
    const int i = blockIdx.x * 256 + threadIdx.x;
    if (i < 4096) {
        const float tot = g_part[i * 4 + 0] + g_part[i * 4 + 1]
                        + g_part[i * 4 + 2] + g_part[i * 4 + 3];
        const float bx = 5.0f * tot;
        const float sp = (fmaxf(bx, 0.0f) + log1pf(expf(-fabsf(bx)))) * 0.2f;
        out[i] = sp * mask[i];
    }
}

extern "C" void kernel_launch(void* const* d_in, const int* in_sizes, int n_in,
                              void* d_out, int out_size)
{
    const float* rep  = (const float*)d_in[0];
    const float* geo  = (const float*)d_in[1];
    const float* mask = (const float*)d_in[2];
    const float* W1   = (const float*)d_in[3];
    const float* W2   = (const float*)d_in[4];
    const float* W3   = (const float*)d_in[5];
    float* out = (float*)d_out;

    cudaFuncSetAttribute(build_table_kernel,
                         cudaFuncAttributeMaxDynamicSharedMemorySize, BSMEM_BYTES);
    cudaFuncSetAttribute(main_kernel,
                         cudaFuncAttributeMaxDynamicSharedMemorySize, MSMEM_BYTES);

    build_table_kernel<<<56, 512, BSMEM_BYTES>>>(W1, W2, W3);
    main_kernel<<<256, 512, MSMEM_BYTES>>>(rep, geo, mask);
    finish_kernel<<<16, 256>>>(mask, out);
}

// round 17
// speedup vs baseline: 3.6874x; 1.1522x over previous
#include <cuda_runtime.h>
#include <cuda_fp16.h>
#include <math.h>

// OutputNetwork, in-SMEM factored pipeline (v3):
//  K1 build: tables on kink-aligned grid h=step/6; W2/W3 staged TRANSPOSED
//     (row-major per output neuron, pad 132) -> float4 dot loops, 4-acc ILP.
//  K2 main: CTA = (z, b-quarter), 2 CTAs/SM. Gs b-stride padded to 2242
//     halves (odd word count) -> conflict-free mma scatter + interp loads.
//  K3 finish: sum 4 partials, softplus, mask.

#define NLIVE 193
#define GR    224
#define GSTR  2242        // halves per b in Gs (GR*10 + 2 pad; odd word count)

__device__ __half g_tab0h[GR * 72];
__device__ __half g_tab1h[GR * 40];
__device__ __half g_tab2h[GR * 24];
__device__ float  g_part[16384];

// ---- build kernel SMEM (floats): W2t[128][132], W3t[112][132], h1s/h2s[4][132]
#define B_W2T  0
#define B_W3T  16896
#define B_H1   31680
#define B_H2   32208
#define BSMEM_BYTES (32736 * 4)

// ---- main kernel SMEM (bytes) ----
#define GS_OFF   0         // Gs [16][GSTR] half = 71744
#define TB_OFF   71744     // Tb up to [224][72] half = 32256
#define AS_OFF   104000    // As [16][240] half = 7680
#define GEO_OFF  111680    // 192 floats
#define FS_OFF   112448
#define MSMEM_BYTES 112480

__device__ __forceinline__ unsigned smem_u32(const void* p) {
    unsigned a;
    asm("{ .reg .u64 t; cvta.to.shared.u64 t, %1; cvt.u32.u64 %0, t; }" : "=r"(a) : "l"(p));
    return a;
}
__device__ __forceinline__ void ldm4(unsigned& r0, unsigned& r1, unsigned& r2, unsigned& r3,
                                     unsigned addr) {
    asm volatile("ldmatrix.sync.aligned.m8n8.x4.shared.b16 {%0, %1, %2, %3}, [%4];"
                 : "=r"(r0), "=r"(r1), "=r"(r2), "=r"(r3) : "r"(addr));
}
__device__ __forceinline__ void mma4(float* c, unsigned a0, unsigned a1, unsigned a2,
                                     unsigned a3, unsigned b0, unsigned b1) {
    asm volatile("mma.sync.aligned.m16n8k16.row.col.f32.f16.f16.f32 "
                 "{%0, %1, %2, %3}, {%4, %5, %6, %7}, {%8, %9}, {%0, %1, %2, %3};"
                 : "+f"(c[0]), "+f"(c[1]), "+f"(c[2]), "+f"(c[3])
                 : "r"(a0), "r"(a1), "r"(a2), "r"(a3), "r"(b0), "r"(b1));
}
__device__ __forceinline__ float ssp_precise(float x) {
    float bx = 5.0f * x;
    return (fmaxf(bx, 0.0f) + log1pf(expf(-fabsf(bx))) - 0.69314718055994531f) * 0.2f;
}

// ============================ K1: build tables ============================
__global__ void __launch_bounds__(512, 1)
build_table_kernel(const float* __restrict__ W1,
                   const float* __restrict__ W2,
                   const float* __restrict__ W3)
{
    extern __shared__ float bs[];
    float* W2t = bs + B_W2T;      // [128 out][132]
    float* W3t = bs + B_W3T;      // [112 out][132]
    float* h1s = bs + B_H1;       // [4][132]
    float* h2s = bs + B_H2;       // [4][132]

    const int t  = threadIdx.x;
    const int rg = t >> 7;
    const int tl = t & 127;

    // transpose-stage weights (coalesced reads)
    for (int i = t; i < 16384; i += 512) {
        const int k = i >> 7, n = i & 127;
        W2t[n * 132 + k] = W2[i];
    }
    for (int i = t; i < 14336; i += 512) {
        const int k = i / 112, n = i - k * 112;
        W3t[n * 132 + k] = W3[i];
    }
    __syncthreads();

    const float RS32  = 0.17677669529663687f;
    const float RS128 = 0.08838834764831843f;

    const int row = blockIdx.x * 4 + rg;     // 0..223
    const bool live = (row < NLIVE);

    // 2-sparse cosine basis at node (centers every 6 nodes)
    const int i0 = row / 6;
    const float d0 = (float)(row - 6 * i0) * (1.0f / 6.0f);
    float sv, cv;
    sincosf(1.5707963267948966f * d0, &sv, &cv);
    const float c0 = (i0 <= 31) ? cv : 0.0f;
    const float c1 = (i0 <= 30) ? sv : 0.0f;
    const int ia = (i0 > 31) ? 31 : i0;
    const int ib = (i0 + 1 > 31) ? 31 : (i0 + 1);
    const float pre = (c0 * W1[ia * 128 + tl] + c1 * W1[ib * 128 + tl]) * RS32;
    h1s[rg * 132 + tl] = ssp_precise(pre);
    __syncthreads();

    // h2[tl] = ssp( sum_k h1[k] * W2t[tl][k] / sqrt(128) ), float4 + 4 accs
    {
        float a0 = 0.f, a1 = 0.f, a2 = 0.f, a3 = 0.f;
        const float* hrow = h1s + rg * 132;
        const float* wrow = W2t + tl * 132;
        #pragma unroll 8
        for (int k = 0; k < 128; k += 4) {
            const float4 h = *(const float4*)(hrow + k);
            const float4 wv = *(const float4*)(wrow + k);
            a0 = fmaf(h.x, wv.x, a0);
            a1 = fmaf(h.y, wv.y, a1);
            a2 = fmaf(h.z, wv.z, a2);
            a3 = fmaf(h.w, wv.w, a3);
        }
        h2s[rg * 132 + tl] = ssp_precise(((a0 + a1) + (a2 + a3)) * RS128);
    }
    __syncthreads();

    if (tl < 112) {
        float a0 = 0.f, a1 = 0.f, a2 = 0.f, a3 = 0.f;
        const float* hrow = h2s + rg * 132;
        const float* wrow = W3t + tl * 132;
        #pragma unroll 8
        for (int k = 0; k < 128; k += 4) {
            const float4 h = *(const float4*)(hrow + k);
            const float4 wv = *(const float4*)(wrow + k);
            a0 = fmaf(h.x, wv.x, a0);
            a1 = fmaf(h.y, wv.y, a1);
            a2 = fmaf(h.z, wv.z, a2);
            a3 = fmaf(h.w, wv.w, a3);
        }
        const float norm = (tl < 64) ? 0.125f
                         : (tl < 96) ? 0.10206207261596575f
                                     : 0.11180339887498948f;
        const float valf = ((a0 + a1) + (a2 + a3)) * RS128 * norm;
        const __half v = __float2half_rn(live ? valf : 0.0f);
        if (tl < 64)      g_tab0h[row * 72 + tl] = v;
        else if (tl < 96) g_tab1h[row * 40 + (tl - 64)] = v;
        else              g_tab2h[row * 24 + (tl - 96)] = v;
    }
}

// ============================ K2: contract + main ============================
__global__ void __launch_bounds__(512, 2)
main_kernel(const float* __restrict__ rep,
            const float* __restrict__ geo,
            const float* __restrict__ mask)
{
    extern __shared__ char smc[];
    __half* Gs   = (__half*)(smc + GS_OFF);   // [16 b][GSTR]
    __half* Tb   = (__half*)(smc + TB_OFF);
    __half* As   = (__half*)(smc + AS_OFF);   // [16][240]
    float*  geoS = (float*)(smc + GEO_OFF);
    float*  fsS  = (float*)(smc + FS_OFF);

    const int t  = threadIdx.x;
    const int z  = blockIdx.x >> 2;
    const int bq = blockIdx.x & 3;

    if (t < 32) {
        float m = mask[z * 64 + t] + mask[z * 64 + 32 + t];
        #pragma unroll
        for (int o = 16; o > 0; o >>= 1) m += __shfl_xor_sync(0xffffffff, m, o);
        if (t == 0) fsS[0] = rsqrtf(m);
    }
    if (t < 192) geoS[t] = geo[z * 192 + t];
    __syncthreads();
    const float fs = fsS[0];

    // ---- stage As: feats (channel-contiguous cols, fp16, fscale folded) ----
    if (t < 480) {
        const int col = t % 240;
        const int bs0 = t / 240;
        int fj;
        if (col < 64)       fj = col;
        else if (col < 160) fj = 64 + 3 * ((col - 64) & 31) + ((col - 64) >> 5);
        else                fj = 160 + 5 * ((col - 160) & 15) + ((col - 160) >> 4);
        #pragma unroll
        for (int b = bs0; b < 16; b += 2)
            As[b * 240 + col] =
                __float2half_rn(fs * rep[(size_t)(z * 64 + bq * 16 + b) * 240 + fj]);
    }

    const int w    = t >> 5;
    const int lane = t & 31;
    const unsigned AsU = smem_u32(As);
    const unsigned TbU = smem_u32(Tb);
    const int mi = lane >> 3, l7 = lane & 7;
    const int ar  = (mi & 1) * 8 + l7;
    const int ac  = (mi >> 1) * 8;
    const int bk  = (mi & 1) * 8;
    const int bts = mi >> 1;
    const int rb  = lane >> 2, cq = lane & 3;

    // ---- 3 sub-phases: stage T, mma channels, scatter to Gs ----
    #pragma unroll 1
    for (int ph = 0; ph < 3; ph++) {
        const int bstride = (ph == 0) ? 72 : ((ph == 1) ? 40 : 24);
        const int n4      = (ph == 0) ? 2016 : ((ph == 1) ? 1120 : 672);
        const __half* gsrc = (ph == 0) ? g_tab0h : ((ph == 1) ? g_tab1h : g_tab2h);
        __syncthreads();
        {
            const uint4* s4 = (const uint4*)gsrc;
            uint4* d4 = (uint4*)Tb;
            for (int i = t; i < n4; i += 512) d4[i] = s4[i];
        }
        __syncthreads();

        if (w < 7) {
            const int nch    = (ph == 0) ? 1 : ((ph == 1) ? 3 : 5);
            const int ksteps = (ph == 0) ? 4 : ((ph == 1) ? 2 : 1);
            const int ch0    = (ph == 0) ? 0 : ((ph == 1) ? 1 : 4);
            const int ab0    = (ph == 0) ? 0 : ((ph == 1) ? 64 : 160);
            #pragma unroll 1
            for (int c = 0; c < nch; c++) {
                const int abase = ab0 + c * (ksteps * 16);
                const int ch = ch0 + c;
                float acc[4][4];
                #pragma unroll
                for (int i = 0; i < 4; i++) {
                    acc[i][0] = 0.f; acc[i][1] = 0.f; acc[i][2] = 0.f; acc[i][3] = 0.f;
                }
                #pragma unroll 4
                for (int ks = 0; ks < 4; ks++) {
                    if (ks >= ksteps) break;
                    unsigned a0, a1, a2, a3;
                    ldm4(a0, a1, a2, a3,
                         AsU + (unsigned)((ar * 240 + abase + ks * 16 + ac) * 2));
                    #pragma unroll
                    for (int p = 0; p < 2; p++) {
                        unsigned r0, r1, r2, r3;
                        ldm4(r0, r1, r2, r3,
                             TbU + (unsigned)(((w * 32 + (2 * p + bts) * 8 + l7) * bstride
                                               + ks * 16 + bk) * 2));
                        mma4(acc[2 * p],     a0, a1, a2, a3, r0, r1);
                        mma4(acc[2 * p + 1], a0, a1, a2, a3, r2, r3);
                    }
                }
                #pragma unroll
                for (int tile = 0; tile < 4; tile++) {
                    const int n0 = w * 32 + tile * 8 + 2 * cq;
                    Gs[rb * GSTR + n0 * 10 + ch]            = __float2half_rn(acc[tile][0]);
                    Gs[rb * GSTR + (n0 + 1) * 10 + ch]      = __float2half_rn(acc[tile][1]);
                    Gs[(rb + 8) * GSTR + n0 * 10 + ch]      = __float2half_rn(acc[tile][2]);
                    Gs[(rb + 8) * GSTR + (n0 + 1) * 10 + ch]= __float2half_rn(acc[tile][3]);
                }
            }
        }
    }
    __syncthreads();

    // ---- hot loop: warp w handles a = 4w..4w+3; lanes = 4a x 8b; 2 b-iters ----
    const int aloc = lane >> 3;
    const int a    = 4 * w + aloc;
    const int bl0  = lane & 7;
    const float gax = geoS[a * 3 + 0];
    const float gay = geoS[a * 3 + 1];
    const float gaz = geoS[a * 3 + 2];

    const float S3  = 1.7320508075688772f;
    const float S5  = 2.2360679774997896f;
    const float S15 = 3.872983346207417f;

    float tot = 0.0f;
    #pragma unroll
    for (int ii = 0; ii < 2; ii++) {
        const int bl = bl0 + 8 * ii;
        const int bg = bq * 16 + bl;
        const float rx = gax - geoS[bg * 3 + 0];
        const float ry = gay - geoS[bg * 3 + 1];
        const float rz = gaz - geoS[bg * 3 + 2];
        const float r2 = rx * rx + ry * ry + rz * rz;
        const float r  = sqrtf(fmaxf(r2, 1e-12f));
        const float nz = (r2 > 1e-10f) ? 1.0f : 0.0f;
        const float inv = 1.0f / r;
        const float xh = rx * inv, yh = ry * inv, zh = rz * inv;
        float yv[8];
        yv[0] = S3 * xh * nz;
        yv[1] = S3 * yh * nz;
        yv[2] = S3 * zh * nz;
        yv[3] = S15 * xh * yh * nz;
        yv[4] = S15 * yh * zh * nz;
        yv[5] = 0.5f * S5 * (3.0f * zh * zh - 1.0f) * nz;
        yv[6] = S15 * xh * zh * nz;
        yv[7] = 0.5f * S15 * (xh * xh - yh * yh) * nz;

        float u = r * 18.6f;                     // node units (h = step/6)
        const float sup = (u < 192.0f) ? 1.0f : 0.0f;
        u = fminf(u, 191.99f);
        int sg = (int)(u * 0.16666667f);
        sg = (sg > 31) ? 31 : sg;
        const float xi = u - 6.0f * (float)sg;
        int s0 = (int)xi - 2;
        s0 = (s0 < 0) ? 0 : ((s0 > 1) ? 1 : s0);
        const float tt = xi - (float)s0;
        const int gs = 6 * sg + s0;

        const float p0 = tt,        p1 = tt - 1.0f, p2 = tt - 2.0f;
        const float p3 = tt - 3.0f, p4 = tt - 4.0f, p5 = tt - 5.0f;
        const float pr2 = p0 * p1, pr3 = pr2 * p2, pr4 = pr3 * p3, pr5 = pr4 * p4;
        const float sf3 = p4 * p5, sf2 = p3 * sf3, sf1 = p2 * sf2, sf0 = p1 * sf1;
        float wgt[6];
        wgt[0] = sup * (-8.3333333333e-3f) * sf0;
        wgt[1] = sup * ( 4.1666666667e-2f) * p0 * sf1;
        wgt[2] = sup * (-8.3333333333e-2f) * pr2 * sf2;
        wgt[3] = sup * ( 8.3333333333e-2f) * pr3 * sf3;
        wgt[4] = sup * (-4.1666666667e-2f) * pr4 * p5;
        wgt[5] = sup * ( 8.3333333333e-3f) * pr5;

        const __half* gp = Gs + bl * GSTR + gs * 10;
        float R[9];
        #pragma unroll
        for (int c = 0; c < 9; c++) R[c] = 0.0f;
        #pragma unroll
        for (int k = 0; k < 6; k++) {
            const unsigned* hp = (const unsigned*)(gp + k * 10);
            const float wk = wgt[k];
            float2 c01 = __half22float2(*(const __half2*)&hp[0]);
            float2 c23 = __half22float2(*(const __half2*)&hp[1]);
            float2 c45 = __half22float2(*(const __half2*)&hp[2]);
            float2 c67 = __half22float2(*(const __half2*)&hp[3]);
            float2 c8x = __half22float2(*(const __half2*)&hp[4]);
            R[0] = fmaf(wk, c01.x, R[0]);
            R[1] = fmaf(wk, c01.y, R[1]);
            R[2] = fmaf(wk, c23.x, R[2]);
            R[3] = fmaf(wk, c23.y, R[3]);
            R[4] = fmaf(wk, c45.x, R[4]);
            R[5] = fmaf(wk, c45.y, R[5]);
            R[6] = fmaf(wk, c67.x, R[6]);
            R[7] = fmaf(wk, c67.y, R[7]);
            R[8] = fmaf(wk, c8x.x, R[8]);
        }
        float ct = R[0];
        ct = fmaf(yv[0], R[1], ct);
        ct = fmaf(yv[1], R[2], ct);
        ct = fmaf(yv[2], R[3], ct);
        ct = fmaf(yv[3], R[4], ct);
        ct = fmaf(yv[4], R[5], ct);
        ct = fmaf(yv[5], R[6], ct);
        ct = fmaf(yv[6], R[7], ct);
        ct = fmaf(yv[7], R[8], ct);
        tot += ct;
    }

    tot += __shfl_xor_sync(0xffffffff, tot, 1);
    tot += __shfl_xor_sync(0xffffffff, tot, 2);
    tot += __shfl_xor_sync(0xffffffff, tot, 4);
    if ((lane & 7) == 0)
        g_part[(z * 64 + a) * 4 + bq] = tot;
}

// ============================ K3: finish ============================
__global__ void __launch_bounds__(256)
finish_kernel(const float* __restrict__ mask, float* __restrict__ out)
{
    const int i = blockIdx.x * 256 + threadIdx.x;
    if (i < 4096) {
        const float tot = g_part[i * 4 + 0] + g_part[i * 4 + 1]
                        + g_part[i * 4 + 2] + g_part[i * 4 + 3];
        const float bx = 5.0f * tot;
        const float sp = (fmaxf(bx, 0.0f) + log1pf(expf(-fabsf(bx)))) * 0.2f;
        out[i] = sp * mask[i];
    }
}

extern "C" void kernel_launch(void* const* d_in, const int* in_sizes, int n_in,
                              void* d_out, int out_size)
{
    const float* rep  = (const float*)d_in[0];
    const float* geo  = (const float*)d_in[1];
    const float* mask = (const float*)d_in[2];
    const float* W1   = (const float*)d_in[3];
    const float* W2   = (const float*)d_in[4];
    const float* W3   = (const float*)d_in[5];
    float* out = (float*)d_out;

    cudaFuncSetAttribute(build_table_kernel,
                         cudaFuncAttributeMaxDynamicSharedMemorySize, BSMEM_BYTES);
    cudaFuncSetAttribute(main_kernel,
                         cudaFuncAttributeMaxDynamicSharedMemorySize, MSMEM_BYTES);

    build_table_kernel<<<56, 512, BSMEM_BYTES>>>(W1, W2, W3);
    main_kernel<<<256, 512, MSMEM_BYTES>>>(rep, geo, mask);
    finish_kernel<<<16, 256>>>(mask, out);
}